// round 5
// baseline (speedup 1.0000x reference)
#include <cuda_runtime.h>
#include <cuda_bf16.h>

#define Cdim   128
#define HW     102400          // 320*320
#define APITCH 104             // act/epi/t pitch (elems): 208B rows, conflict-free ldmatrix.trans

// fragment-order A operands: [tile][ks][lane][4 x u32]
__device__ __align__(16) unsigned g_WmainFrag[8 * 16 * 32 * 4];  // 64KB
__device__ __align__(16) unsigned g_Wdm1Frag[2 * 8 * 32 * 4];    // 8KB
__device__ __align__(16) unsigned g_Wdm2Frag[8 * 2 * 32 * 4];    // 2KB

__device__ __forceinline__ unsigned pack_bf2f(float lo, float hi) {
    unsigned u;
    asm("cvt.rn.bf16x2.f32 %0, %1, %2;" : "=r"(u) : "f"(hi), "f"(lo));
    return u;
}

// One prologue kernel: fold W_fuse@{Wh_pw,Wv_pw} and write ALL mma A-fragments
// directly in fragment order. Blocks 0..127: Wmain row o. Block 128: dm1. 129: dm2.
__global__ void precompute_pack_kernel(const float* __restrict__ w_h_pw,
                                       const float* __restrict__ w_v_pw,
                                       const float* __restrict__ w_dm1,
                                       const float* __restrict__ w_dm2,
                                       const float* __restrict__ w_fuse) {
    __shared__ float wf[256];
    int o = blockIdx.x;
    int tid = threadIdx.x;            // 256
    if (o < 128) {
        wf[tid] = w_fuse[o * 256 + tid];
        __syncthreads();
        int s = tid >> 7, t = tid & 127;
        const float* mat = s ? w_v_pw : w_h_pw;
        const float* wrow = wf + s * 128;
        float acc = 0.f;
        #pragma unroll 16
        for (int j = 0; j < 128; ++j)
            acc += wrow[j] * __ldg(mat + j * 128 + t);
        float hi = __shfl_down_sync(0xffffffffu, acc, 1);
        if ((t & 1) == 0) {
            int col = s * 128 + t;
            int rt = o & 15, ot = o >> 4;
            int ks = col >> 4, ct = col & 15;
            int lane_f = (rt & 7) * 4 + ((ct & 7) >> 1);
            int j = (rt >> 3) | ((ct >> 3) << 1);
            g_WmainFrag[((ot * 16 + ks) * 32 + lane_f) * 4 + j] = pack_bf2f(acc, hi);
        }
    } else if (o == 128) {
        for (int idx = tid; idx < 2048; idx += 256) {   // dm1 frags [2][8][32][4]
            int j = idx & 3, lane = (idx >> 2) & 31, ks = (idx >> 7) & 7, mt = idx >> 10;
            int row = mt * 16 + (lane >> 2) + (j & 1) * 8;
            int col = ks * 16 + (lane & 3) * 2 + (j >> 1) * 8;
            g_Wdm1Frag[idx] = pack_bf2f(w_dm1[row * 128 + col], w_dm1[row * 128 + col + 1]);
        }
    } else {
        for (int idx = tid; idx < 512; idx += 256) {    // dm2 frags [8][2][32][4]
            int j = idx & 3, lane = (idx >> 2) & 31, ks = (idx >> 7) & 1, ot = idx >> 8;
            int row = ot * 16 + (lane >> 2) + (j & 1) * 8;
            int col = ks * 16 + (lane & 3) * 2 + (j >> 1) * 8;
            g_Wdm2Frag[idx] = pack_bf2f(w_dm2[row * 32 + col], w_dm2[row * 32 + col + 1]);
        }
    }
}

// ---- mma helpers ----
__device__ __forceinline__ void ldmatrix_x2t(unsigned &r0, unsigned &r1, unsigned addr) {
    asm volatile("ldmatrix.sync.aligned.m8n8.x2.trans.shared.b16 {%0,%1}, [%2];"
                 : "=r"(r0), "=r"(r1) : "r"(addr));
}
__device__ __forceinline__ void mma_bf16(float &c0, float &c1, float &c2, float &c3,
                                         unsigned a0, unsigned a1, unsigned a2, unsigned a3,
                                         unsigned b0, unsigned b1) {
    asm volatile("mma.sync.aligned.m16n8k16.row.col.f32.bf16.bf16.f32 "
                 "{%0,%1,%2,%3}, {%4,%5,%6,%7}, {%8,%9}, {%0,%1,%2,%3};"
                 : "+f"(c0), "+f"(c1), "+f"(c2), "+f"(c3)
                 : "r"(a0), "r"(a1), "r"(a2), "r"(a3), "r"(b0), "r"(b1));
}

__device__ __forceinline__ float lrelu(float x) { return fmaxf(x, 0.1f * x); }

__device__ __forceinline__ void conv5(const float w[5],
                                      float x0, float x1, float x2, float x3, float x4,
                                      float o[5]) {
    o[0] = w[2]*x0 + w[3]*x1 + w[4]*x2;
    o[1] = w[1]*x0 + w[2]*x1 + w[3]*x2 + w[4]*x3;
    o[2] = w[0]*x0 + w[1]*x1 + w[2]*x2 + w[3]*x3 + w[4]*x4;
    o[3] = w[0]*x1 + w[1]*x2 + w[2]*x3 + w[3]*x4;
    o[4] = w[0]*x2 + w[1]*x3 + w[2]*x4;
}

// ---- shared memory (bytes) ----
// 0     : act [256][APITCH] bf16  53248   (d_s aliases after P3)
// 53248 : epi_s [128][APITCH] bf16 26624
// 79872 : t_s   [32][APITCH]  bf16  6656
// total 86528  -> 2 CTAs/SM
#define SMEM_BYTES 86528

__global__ __launch_bounds__(512, 2)
void epi_mma_kernel(const float* __restrict__ x,
                    const float* __restrict__ w_h_dw,
                    const float* __restrict__ w_v_dw,
                    const float* __restrict__ scale_p,
                    float* __restrict__ out) {
    extern __shared__ char smem[];
    __nv_bfloat16* act   = (__nv_bfloat16*)(smem);
    __nv_bfloat16* epi_s = (__nv_bfloat16*)(smem + 53248);
    __nv_bfloat16* t_s   = (__nv_bfloat16*)(smem + 79872);
    __nv_bfloat16* d_s   = act;   // alias; act dead after P3

    const int tid  = threadIdx.x;
    const int lane = tid & 31;
    const int warp = tid >> 5;
    const int C0 = blockIdx.x * 20;
    const int R0 = blockIdx.y * 5;
    const int b  = blockIdx.z;
    const float* xb = x + (long)b * Cdim * HW;

    // ---- P2: depthwise 1x5 / 5x1 (block-local) straight from global + lrelu ----
    {
        const int c = tid >> 2, blk = tid & 3;
        float wh[5], wv[5];
        #pragma unroll
        for (int k = 0; k < 5; ++k) { wh[k] = w_h_dw[c * 5 + k]; wv[k] = w_v_dw[c * 5 + k]; }
        const float* xr = xb + (long)c * HW + (long)R0 * 320 + C0 + blk * 5;
        float xv[5][5];
        #pragma unroll
        for (int r = 0; r < 5; ++r)
            #pragma unroll
            for (int j = 0; j < 5; ++j) xv[r][j] = xr[r * 320 + j];

        __nv_bfloat16* ah = act + c * APITCH + blk * 5;
        __nv_bfloat16* av = act + (128 + c) * APITCH + blk * 5;
        #pragma unroll
        for (int r = 0; r < 5; ++r) {       // horizontal, row r
            float o[5];
            conv5(wh, xv[r][0], xv[r][1], xv[r][2], xv[r][3], xv[r][4], o);
            #pragma unroll
            for (int j = 0; j < 5; ++j) ah[r * 20 + j] = __float2bfloat16(lrelu(o[j]));
        }
        #pragma unroll
        for (int j = 0; j < 5; ++j) {       // vertical, column j
            float o[5];
            conv5(wv, xv[0][j], xv[1][j], xv[2][j], xv[3][j], xv[4][j], o);
            #pragma unroll
            for (int r = 0; r < 5; ++r) av[r * 20 + j] = __float2bfloat16(lrelu(o[r]));
        }
    }
    if (tid < 256) {   // zero pad act cols 100..103
        *(__nv_bfloat162*)(act + tid * APITCH + 100) = __floats2bfloat162_rn(0.f, 0.f);
        *(__nv_bfloat162*)(act + tid * APITCH + 102) = __floats2bfloat162_rn(0.f, 0.f);
    }
    __syncthreads();

    // ---- P3: epi[128][104] = Wm[128][256] @ act[256][104] ----
    // warp = (mhalf, ngroup): 4 m-tiles x {2,2,2,2,2,1,1,1} n-tiles
    const int mhalf = warp & 1;
    const int g     = warp >> 1;
    const int nt0   = (g < 5) ? g * 2 : 10 + (g - 5);
    const int ncnt  = (g < 5) ? 2 : 1;
    const int r  = lane >> 2, cp = (lane & 3) * 2;

    {
        float acc[4][2][4];
        #pragma unroll
        for (int mi = 0; mi < 4; ++mi)
            #pragma unroll
            for (int j = 0; j < 2; ++j)
                acc[mi][j][0] = acc[mi][j][1] = acc[mi][j][2] = acc[mi][j][3] = 0.f;

        const uint4* fragA = ((const uint4*)g_WmainFrag) + (mhalf * 4) * 16 * 32 + lane;
        unsigned bBase = (unsigned)__cvta_generic_to_shared(act)
                         + ((lane & 15) * APITCH + nt0 * 8) * 2;
        #pragma unroll
        for (int ks = 0; ks < 16; ++ks) {
            unsigned b0[2], b1[2];
            unsigned bRow = bBase + ks * 16 * APITCH * 2;
            ldmatrix_x2t(b0[0], b0[1], bRow);
            if (ncnt == 2) ldmatrix_x2t(b1[0], b1[1], bRow + 16);
            #pragma unroll
            for (int mi = 0; mi < 4; ++mi) {
                uint4 a = fragA[(mi * 16 + ks) * 32];
                mma_bf16(acc[mi][0][0], acc[mi][0][1], acc[mi][0][2], acc[mi][0][3],
                         a.x, a.y, a.z, a.w, b0[0], b0[1]);
                if (ncnt == 2)
                    mma_bf16(acc[mi][1][0], acc[mi][1][1], acc[mi][1][2], acc[mi][1][3],
                             a.x, a.y, a.z, a.w, b1[0], b1[1]);
            }
        }
        #pragma unroll
        for (int mi = 0; mi < 4; ++mi) {
            int o0 = (mhalf * 4 + mi) * 16;
            #pragma unroll
            for (int j = 0; j < 2; ++j) {
                if (j < ncnt) {
                    int n = (nt0 + j) * 8 + cp;
                    *(__nv_bfloat162*)(epi_s + (o0 + r) * APITCH + n)
                        = __floats2bfloat162_rn(acc[mi][j][0], acc[mi][j][1]);
                    *(__nv_bfloat162*)(epi_s + (o0 + r + 8) * APITCH + n)
                        = __floats2bfloat162_rn(acc[mi][j][2], acc[mi][j][3]);
                }
            }
        }
    }
    __syncthreads();   // epi ready; act dead

    // ---- P4: dm1 t[32][104] = lrelu(Wdm1[32][128] @ epi) ----
    {
        int mt = warp & 1, m0 = mt * 16;
        int nt1 = warp >> 1;
        int nt2 = nt1 + 8;
        bool has2 = (warp < 10);
        float c1[4] = {0.f, 0.f, 0.f, 0.f}, c2[4] = {0.f, 0.f, 0.f, 0.f};
        const uint4* wf1 = ((const uint4*)g_Wdm1Frag) + mt * 8 * 32 + lane;
        unsigned bB = (unsigned)__cvta_generic_to_shared(epi_s)
                      + ((lane & 15) * APITCH) * 2;
        #pragma unroll
        for (int ks = 0; ks < 8; ++ks) {
            uint4 a = wf1[ks * 32];
            unsigned bRow = bB + ks * 16 * APITCH * 2;
            unsigned b0, b1;
            ldmatrix_x2t(b0, b1, bRow + nt1 * 16);
            mma_bf16(c1[0], c1[1], c1[2], c1[3], a.x, a.y, a.z, a.w, b0, b1);
            if (has2) {
                ldmatrix_x2t(b0, b1, bRow + nt2 * 16);
                mma_bf16(c2[0], c2[1], c2[2], c2[3], a.x, a.y, a.z, a.w, b0, b1);
            }
        }
        {
            int n = nt1 * 8 + cp;
            *(__nv_bfloat162*)(t_s + (m0 + r) * APITCH + n)
                = __floats2bfloat162_rn(lrelu(c1[0]), lrelu(c1[1]));
            *(__nv_bfloat162*)(t_s + (m0 + r + 8) * APITCH + n)
                = __floats2bfloat162_rn(lrelu(c1[2]), lrelu(c1[3]));
        }
        if (has2) {
            int n = nt2 * 8 + cp;
            *(__nv_bfloat162*)(t_s + (m0 + r) * APITCH + n)
                = __floats2bfloat162_rn(lrelu(c2[0]), lrelu(c2[1]));
            *(__nv_bfloat162*)(t_s + (m0 + r + 8) * APITCH + n)
                = __floats2bfloat162_rn(lrelu(c2[2]), lrelu(c2[3]));
        }
    }
    __syncthreads();

    // ---- P5: dm2 d[128][104] = sigmoid(Wdm2[128][32] @ t), same tiling as P3 ----
    {
        float acc[4][2][4];
        #pragma unroll
        for (int mi = 0; mi < 4; ++mi)
            #pragma unroll
            for (int j = 0; j < 2; ++j)
                acc[mi][j][0] = acc[mi][j][1] = acc[mi][j][2] = acc[mi][j][3] = 0.f;

        const uint4* fragA = ((const uint4*)g_Wdm2Frag) + (mhalf * 4) * 2 * 32 + lane;
        unsigned bBase = (unsigned)__cvta_generic_to_shared(t_s)
                         + ((lane & 15) * APITCH + nt0 * 8) * 2;
        #pragma unroll
        for (int ks = 0; ks < 2; ++ks) {
            unsigned b0[2], b1[2];
            unsigned bRow = bBase + ks * 16 * APITCH * 2;
            ldmatrix_x2t(b0[0], b0[1], bRow);
            if (ncnt == 2) ldmatrix_x2t(b1[0], b1[1], bRow + 16);
            #pragma unroll
            for (int mi = 0; mi < 4; ++mi) {
                uint4 a = fragA[(mi * 2 + ks) * 32];
                mma_bf16(acc[mi][0][0], acc[mi][0][1], acc[mi][0][2], acc[mi][0][3],
                         a.x, a.y, a.z, a.w, b0[0], b0[1]);
                if (ncnt == 2)
                    mma_bf16(acc[mi][1][0], acc[mi][1][1], acc[mi][1][2], acc[mi][1][3],
                             a.x, a.y, a.z, a.w, b1[0], b1[1]);
            }
        }
        #pragma unroll
        for (int mi = 0; mi < 4; ++mi) {
            int o0 = (mhalf * 4 + mi) * 16;
            #pragma unroll
            for (int j = 0; j < 2; ++j) {
                if (j < ncnt) {
                    int n = (nt0 + j) * 8 + cp;
                    float d0 = 1.f / (1.f + __expf(-acc[mi][j][0]));
                    float d1 = 1.f / (1.f + __expf(-acc[mi][j][1]));
                    float d2 = 1.f / (1.f + __expf(-acc[mi][j][2]));
                    float d3 = 1.f / (1.f + __expf(-acc[mi][j][3]));
                    *(__nv_bfloat162*)(d_s + (o0 + r) * APITCH + n)
                        = __floats2bfloat162_rn(d0, d1);
                    *(__nv_bfloat162*)(d_s + (o0 + r + 8) * APITCH + n)
                        = __floats2bfloat162_rn(d2, d3);
                }
            }
        }
    }
    __syncthreads();

    // ---- P6: out = x + scale * epi * d (float4, x re-read via L2) ----
    const float s = scale_p[0];
    float* ob = out + (long)b * Cdim * HW;
    #pragma unroll
    for (int it = 0; it < 7; ++it) {
        int idx = tid + it * 512;
        if (idx < 3200) {
            int c = idx / 25, rem = idx - c * 25;
            int rr = rem / 5, v = rem - rr * 5;
            long gg = (long)c * HW + (long)(R0 + rr) * 320 + C0 + v * 4;
            int pb = c * APITCH + rr * 20 + v * 4;
            float4 xv = *(const float4*)(xb + gg);
            __nv_bfloat162 ea = ((const __nv_bfloat162*)(epi_s + pb))[0];
            __nv_bfloat162 eb = ((const __nv_bfloat162*)(epi_s + pb))[1];
            __nv_bfloat162 da = ((const __nv_bfloat162*)(d_s + pb))[0];
            __nv_bfloat162 db = ((const __nv_bfloat162*)(d_s + pb))[1];
            float2 e0 = __bfloat1622float2(ea), e1 = __bfloat1622float2(eb);
            float2 f0 = __bfloat1622float2(da), f1 = __bfloat1622float2(db);
            xv.x += s * e0.x * f0.x;
            xv.y += s * e0.y * f0.y;
            xv.z += s * e1.x * f1.x;
            xv.w += s * e1.y * f1.y;
            *(float4*)(ob + gg) = xv;
        }
    }
}

extern "C" void kernel_launch(void* const* d_in, const int* in_sizes, int n_in,
                              void* d_out, int out_size) {
    const float* x       = (const float*)d_in[0];
    const float* w_h_dw  = (const float*)d_in[1];
    const float* w_h_pw  = (const float*)d_in[2];
    const float* w_v_dw  = (const float*)d_in[3];
    const float* w_v_pw  = (const float*)d_in[4];
    const float* w_dm1   = (const float*)d_in[5];
    const float* w_dm2   = (const float*)d_in[6];
    const float* w_fuse  = (const float*)d_in[7];
    const float* scale   = (const float*)d_in[8];

    precompute_pack_kernel<<<130, 256>>>(w_h_pw, w_v_pw, w_dm1, w_dm2, w_fuse);

    cudaFuncSetAttribute(epi_mma_kernel,
                         cudaFuncAttributeMaxDynamicSharedMemorySize, SMEM_BYTES);
    dim3 grid(320 / 20, 320 / 5, 2);
    epi_mma_kernel<<<grid, 512, SMEM_BYTES>>>(x, w_h_dw, w_v_dw, scale, (float*)d_out);
}

// round 6
// speedup vs baseline: 1.1783x; 1.1783x over previous
#include <cuda_runtime.h>
#include <cuda_bf16.h>

#define Cdim   128
#define HW     102400          // 320*320
#define APITCH 104             // act/epi/t pitch (elems): 208B rows, conflict-free ldmatrix.trans

// fragment-order A operands: [tile][ks][lane][4 x u32]
__device__ __align__(16) unsigned g_WmainFrag[8 * 16 * 32 * 4];  // 64KB
__device__ __align__(16) unsigned g_Wdm1Frag[2 * 8 * 32 * 4];    // 8KB
__device__ __align__(16) unsigned g_Wdm2Frag[8 * 2 * 32 * 4];    // 2KB

__device__ __forceinline__ unsigned pack_bf2f(float lo, float hi) {
    unsigned u;
    asm("cvt.rn.bf16x2.f32 %0, %1, %2;" : "=r"(u) : "f"(hi), "f"(lo));
    return u;
}

// One prologue kernel: fold W_fuse@{Wh_pw,Wv_pw} and write ALL mma A-fragments
// directly in fragment order. Blocks 0..127: Wmain row o. Block 128: dm1. 129: dm2.
__global__ void precompute_pack_kernel(const float* __restrict__ w_h_pw,
                                       const float* __restrict__ w_v_pw,
                                       const float* __restrict__ w_dm1,
                                       const float* __restrict__ w_dm2,
                                       const float* __restrict__ w_fuse) {
    __shared__ float wf[256];
    int o = blockIdx.x;
    int tid = threadIdx.x;            // 256
    if (o < 128) {
        wf[tid] = w_fuse[o * 256 + tid];
        __syncthreads();
        int s = tid >> 7, t = tid & 127;
        const float* mat = s ? w_v_pw : w_h_pw;
        const float* wrow = wf + s * 128;
        float acc = 0.f;
        #pragma unroll 16
        for (int j = 0; j < 128; ++j)
            acc += wrow[j] * __ldg(mat + j * 128 + t);
        float hi = __shfl_down_sync(0xffffffffu, acc, 1);
        if ((t & 1) == 0) {
            int col = s * 128 + t;
            int rt = o & 15, ot = o >> 4;
            int ks = col >> 4, ct = col & 15;
            int lane_f = (rt & 7) * 4 + ((ct & 7) >> 1);
            int j = (rt >> 3) | ((ct >> 3) << 1);
            g_WmainFrag[((ot * 16 + ks) * 32 + lane_f) * 4 + j] = pack_bf2f(acc, hi);
        }
    } else if (o == 128) {
        for (int idx = tid; idx < 2048; idx += 256) {   // dm1 frags [2][8][32][4]
            int j = idx & 3, lane = (idx >> 2) & 31, ks = (idx >> 7) & 7, mt = idx >> 10;
            int row = mt * 16 + (lane >> 2) + (j & 1) * 8;
            int col = ks * 16 + (lane & 3) * 2 + (j >> 1) * 8;
            g_Wdm1Frag[idx] = pack_bf2f(w_dm1[row * 128 + col], w_dm1[row * 128 + col + 1]);
        }
    } else {
        for (int idx = tid; idx < 512; idx += 256) {    // dm2 frags [8][2][32][4]
            int j = idx & 3, lane = (idx >> 2) & 31, ks = (idx >> 7) & 1, ot = idx >> 8;
            int row = ot * 16 + (lane >> 2) + (j & 1) * 8;
            int col = ks * 16 + (lane & 3) * 2 + (j >> 1) * 8;
            g_Wdm2Frag[idx] = pack_bf2f(w_dm2[row * 32 + col], w_dm2[row * 32 + col + 1]);
        }
    }
}

// ---- mma helpers ----
__device__ __forceinline__ void ldmatrix_x2t(unsigned &r0, unsigned &r1, unsigned addr) {
    asm volatile("ldmatrix.sync.aligned.m8n8.x2.trans.shared.b16 {%0,%1}, [%2];"
                 : "=r"(r0), "=r"(r1) : "r"(addr));
}
__device__ __forceinline__ void mma_bf16(float &c0, float &c1, float &c2, float &c3,
                                         unsigned a0, unsigned a1, unsigned a2, unsigned a3,
                                         unsigned b0, unsigned b1) {
    asm volatile("mma.sync.aligned.m16n8k16.row.col.f32.bf16.bf16.f32 "
                 "{%0,%1,%2,%3}, {%4,%5,%6,%7}, {%8,%9}, {%0,%1,%2,%3};"
                 : "+f"(c0), "+f"(c1), "+f"(c2), "+f"(c3)
                 : "r"(a0), "r"(a1), "r"(a2), "r"(a3), "r"(b0), "r"(b1));
}

__device__ __forceinline__ float lrelu(float x) { return fmaxf(x, 0.1f * x); }

__device__ __forceinline__ void conv5(const float w[5],
                                      float x0, float x1, float x2, float x3, float x4,
                                      float o[5]) {
    o[0] = w[2]*x0 + w[3]*x1 + w[4]*x2;
    o[1] = w[1]*x0 + w[2]*x1 + w[3]*x2 + w[4]*x3;
    o[2] = w[0]*x0 + w[1]*x1 + w[2]*x2 + w[3]*x3 + w[4]*x4;
    o[3] = w[0]*x1 + w[1]*x2 + w[2]*x3 + w[3]*x4;
    o[4] = w[0]*x2 + w[1]*x3 + w[2]*x4;
}

// ---- shared memory layout (bytes) ----
// 0      : act [256][APITCH] bf16  53248   (d_s aliases after P3)
// 53248  : region (53248):
//            sx    f32 [128][104]      53248  (P1/P2 only)
//            epi_s [128][APITCH] bf16  26624  (+0)
//            t_s   [32][APITCH]  bf16   6656  (+26624)
// 106496 : dwg f32[1280]  5120
// total 111616  -> 2 CTAs/SM
#define SMEM_BYTES 111616

__global__ __launch_bounds__(512, 2)
void epi_mma_kernel(const float* __restrict__ x,
                    const float* __restrict__ w_h_dw,
                    const float* __restrict__ w_v_dw,
                    const float* __restrict__ scale_p,
                    float* __restrict__ out) {
    extern __shared__ char smem[];
    __nv_bfloat16* act   = (__nv_bfloat16*)(smem);
    char* region = smem + 53248;
    float* sx            = (float*)(region);
    __nv_bfloat16* epi_s = (__nv_bfloat16*)(region);
    __nv_bfloat16* t_s   = (__nv_bfloat16*)(region + 26624);
    float* dwg = (float*)(smem + 106496);
    __nv_bfloat16* d_s = act;   // alias; act dead after P3

    const int tid  = threadIdx.x;
    const int lane = tid & 31;
    const int warp = tid >> 5;
    const int C0 = blockIdx.x * 20;
    const int R0 = blockIdx.y * 5;
    const int b  = blockIdx.z;
    const float* xb = x + (long)b * Cdim * HW;

    // ---- P1: stage x tile (coalesced float4) + dw weights + zero act pad ----
    #pragma unroll
    for (int it = 0; it < 7; ++it) {
        int idx = tid + it * 512;
        if (idx < 3200) {
            int row = idx / 5, q = idx - row * 5;
            int c = row / 5, r = row - c * 5;
            float4 v = *(const float4*)(xb + (long)c * HW + (R0 + r) * 320 + C0 + q * 4);
            *(float4*)(sx + c * 104 + r * 20 + q * 4) = v;
        }
    }
    for (int idx = tid; idx < 1280; idx += 512)
        dwg[idx] = (idx < 640) ? w_h_dw[idx] : w_v_dw[idx - 640];
    {   // zero act cols 100..103 for all 256 rows
        int k = tid >> 1, q = tid & 1;
        *(__nv_bfloat162*)(act + k * APITCH + 100 + q * 2) = __floats2bfloat162_rn(0.f, 0.f);
    }
    __syncthreads();

    // ---- P2: depthwise 1x5 / 5x1 + lrelu -> act bf16 [K][N] ----
    {
        const int c = tid >> 2, sub = tid & 3;
        float wh[5], wv[5];
        #pragma unroll
        for (int k = 0; k < 5; ++k) { wh[k] = dwg[c * 5 + k]; wv[k] = dwg[640 + c * 5 + k]; }
        const float* sxr = sx + c * 104;
        __nv_bfloat16* ah = act + c * APITCH;
        __nv_bfloat16* av = act + (128 + c) * APITCH;
        #pragma unroll
        for (int i = 0; i < 5; ++i) {
            {   // horizontal: row i, angular block sub
                const float* p = sxr + i * 20 + sub * 5;
                float o[5];
                conv5(wh, p[0], p[1], p[2], p[3], p[4], o);
                __nv_bfloat16* q = ah + i * 20 + sub * 5;
                #pragma unroll
                for (int j = 0; j < 5; ++j) q[j] = __float2bfloat16(lrelu(o[j]));
            }
            {   // vertical: column sub + 4*i
                int col = sub + 4 * i;
                float o[5];
                conv5(wv, sxr[col], sxr[20 + col], sxr[40 + col], sxr[60 + col], sxr[80 + col], o);
                #pragma unroll
                for (int j = 0; j < 5; ++j) av[j * 20 + col] = __float2bfloat16(lrelu(o[j]));
            }
        }
    }
    __syncthreads();   // act ready; sx dead

    // ---- P3: main GEMM epi[128][104] = Wm[128][256] @ act[256][104] ----
    const int otile = warp & 7;
    const int o0    = otile * 16;
    const int nhalf = warp >> 3;
    const int nt0   = nhalf * 7;
    const int ncnt  = 7 - nhalf;
    float acc[7][4];
    #pragma unroll
    for (int j = 0; j < 7; ++j) acc[j][0] = acc[j][1] = acc[j][2] = acc[j][3] = 0.f;

    const uint4* wfA = ((const uint4*)g_WmainFrag) + otile * 16 * 32 + lane;
    unsigned bBase = (unsigned)__cvta_generic_to_shared(act)
                     + ((lane & 15) * APITCH + nt0 * 8) * 2;
    #pragma unroll
    for (int ks = 0; ks < 16; ++ks) {
        uint4 a = wfA[ks * 32];
        unsigned bRow = bBase + ks * 16 * APITCH * 2;
        #pragma unroll
        for (int j = 0; j < 7; ++j) {
            if (j < ncnt) {
                unsigned b0, b1;
                ldmatrix_x2t(b0, b1, bRow + j * 16);
                mma_bf16(acc[j][0], acc[j][1], acc[j][2], acc[j][3],
                         a.x, a.y, a.z, a.w, b0, b1);
            }
        }
    }
    {
        int r = lane >> 2, cp = (lane & 3) * 2;
        #pragma unroll
        for (int j = 0; j < 7; ++j) {
            if (j < ncnt) {
                int n = (nt0 + j) * 8 + cp;
                *(__nv_bfloat162*)(epi_s + (o0 + r) * APITCH + n)
                    = __floats2bfloat162_rn(acc[j][0], acc[j][1]);
                *(__nv_bfloat162*)(epi_s + (o0 + r + 8) * APITCH + n)
                    = __floats2bfloat162_rn(acc[j][2], acc[j][3]);
            }
        }
    }
    __syncthreads();   // epi ready (sx region now epi)

    // ---- P4: dm1 t[32][104] = lrelu(Wdm1[32][128] @ epi) ----
    {
        int mt = warp & 1, m0 = mt * 16;
        int nt1 = warp >> 1;
        int nt2 = nt1 + 8;
        bool has2 = (warp < 10);
        float c1[4] = {0.f, 0.f, 0.f, 0.f}, c2[4] = {0.f, 0.f, 0.f, 0.f};
        const uint4* wf1 = ((const uint4*)g_Wdm1Frag) + mt * 8 * 32 + lane;
        unsigned bB = (unsigned)__cvta_generic_to_shared(epi_s)
                      + ((lane & 15) * APITCH) * 2;
        #pragma unroll
        for (int ks = 0; ks < 8; ++ks) {
            uint4 a = wf1[ks * 32];
            unsigned bRow = bB + ks * 16 * APITCH * 2;
            unsigned b0, b1;
            ldmatrix_x2t(b0, b1, bRow + nt1 * 16);
            mma_bf16(c1[0], c1[1], c1[2], c1[3], a.x, a.y, a.z, a.w, b0, b1);
            if (has2) {
                ldmatrix_x2t(b0, b1, bRow + nt2 * 16);
                mma_bf16(c2[0], c2[1], c2[2], c2[3], a.x, a.y, a.z, a.w, b0, b1);
            }
        }
        int r = lane >> 2, cp = (lane & 3) * 2;
        {
            int n = nt1 * 8 + cp;
            *(__nv_bfloat162*)(t_s + (m0 + r) * APITCH + n)
                = __floats2bfloat162_rn(lrelu(c1[0]), lrelu(c1[1]));
            *(__nv_bfloat162*)(t_s + (m0 + r + 8) * APITCH + n)
                = __floats2bfloat162_rn(lrelu(c1[2]), lrelu(c1[3]));
        }
        if (has2) {
            int n = nt2 * 8 + cp;
            *(__nv_bfloat162*)(t_s + (m0 + r) * APITCH + n)
                = __floats2bfloat162_rn(lrelu(c2[0]), lrelu(c2[1]));
            *(__nv_bfloat162*)(t_s + (m0 + r + 8) * APITCH + n)
                = __floats2bfloat162_rn(lrelu(c2[2]), lrelu(c2[3]));
        }
    }
    __syncthreads();

    // ---- P5: dm2 d[128][104] = sigmoid(Wdm2[128][32] @ t) ----
    {
        float a2c[7][4];
        #pragma unroll
        for (int j = 0; j < 7; ++j) a2c[j][0] = a2c[j][1] = a2c[j][2] = a2c[j][3] = 0.f;
        const uint4* wf2 = ((const uint4*)g_Wdm2Frag) + otile * 2 * 32 + lane;
        unsigned bB = (unsigned)__cvta_generic_to_shared(t_s)
                      + ((lane & 15) * APITCH + nt0 * 8) * 2;
        #pragma unroll
        for (int ks = 0; ks < 2; ++ks) {
            uint4 a = wf2[ks * 32];
            unsigned bRow = bB + ks * 16 * APITCH * 2;
            #pragma unroll
            for (int j = 0; j < 7; ++j) {
                if (j < ncnt) {
                    unsigned b0, b1;
                    ldmatrix_x2t(b0, b1, bRow + j * 16);
                    mma_bf16(a2c[j][0], a2c[j][1], a2c[j][2], a2c[j][3],
                             a.x, a.y, a.z, a.w, b0, b1);
                }
            }
        }
        int r = lane >> 2, cp = (lane & 3) * 2;
        #pragma unroll
        for (int j = 0; j < 7; ++j) {
            if (j < ncnt) {
                int n = (nt0 + j) * 8 + cp;
                float d0 = 1.f / (1.f + __expf(-a2c[j][0]));
                float d1 = 1.f / (1.f + __expf(-a2c[j][1]));
                float d2 = 1.f / (1.f + __expf(-a2c[j][2]));
                float d3 = 1.f / (1.f + __expf(-a2c[j][3]));
                *(__nv_bfloat162*)(d_s + (o0 + r) * APITCH + n)
                    = __floats2bfloat162_rn(d0, d1);
                *(__nv_bfloat162*)(d_s + (o0 + r + 8) * APITCH + n)
                    = __floats2bfloat162_rn(d2, d3);
            }
        }
    }
    __syncthreads();

    // ---- P6: out = x + scale * epi * d (float4, x re-read via L2) ----
    const float s = scale_p[0];
    float* ob = out + (long)b * Cdim * HW;
    #pragma unroll
    for (int it = 0; it < 7; ++it) {
        int idx = tid + it * 512;
        if (idx < 3200) {
            int c = idx / 25, rem = idx - c * 25;
            int r = rem / 5, v = rem - r * 5;
            long g = (long)c * HW + (long)(R0 + r) * 320 + C0 + v * 4;
            int pb = c * APITCH + r * 20 + v * 4;
            float4 xv = *(const float4*)(xb + g);
            __nv_bfloat162 ea = ((const __nv_bfloat162*)(epi_s + pb))[0];
            __nv_bfloat162 eb = ((const __nv_bfloat162*)(epi_s + pb))[1];
            __nv_bfloat162 da = ((const __nv_bfloat162*)(d_s + pb))[0];
            __nv_bfloat162 db = ((const __nv_bfloat162*)(d_s + pb))[1];
            float2 e0 = __bfloat1622float2(ea), e1 = __bfloat1622float2(eb);
            float2 f0 = __bfloat1622float2(da), f1 = __bfloat1622float2(db);
            xv.x += s * e0.x * f0.x;
            xv.y += s * e0.y * f0.y;
            xv.z += s * e1.x * f1.x;
            xv.w += s * e1.y * f1.y;
            *(float4*)(ob + g) = xv;
        }
    }
}

extern "C" void kernel_launch(void* const* d_in, const int* in_sizes, int n_in,
                              void* d_out, int out_size) {
    const float* x       = (const float*)d_in[0];
    const float* w_h_dw  = (const float*)d_in[1];
    const float* w_h_pw  = (const float*)d_in[2];
    const float* w_v_dw  = (const float*)d_in[3];
    const float* w_v_pw  = (const float*)d_in[4];
    const float* w_dm1   = (const float*)d_in[5];
    const float* w_dm2   = (const float*)d_in[6];
    const float* w_fuse  = (const float*)d_in[7];
    const float* scale   = (const float*)d_in[8];

    precompute_pack_kernel<<<130, 256>>>(w_h_pw, w_v_pw, w_dm1, w_dm2, w_fuse);

    cudaFuncSetAttribute(epi_mma_kernel,
                         cudaFuncAttributeMaxDynamicSharedMemorySize, SMEM_BYTES);
    dim3 grid(320 / 20, 320 / 5, 2);
    epi_mma_kernel<<<grid, 512, SMEM_BYTES>>>(x, w_h_dw, w_v_dw, scale, (float*)d_out);
}